// round 1
// baseline (speedup 1.0000x reference)
#include <cuda_runtime.h>
#include <math.h>

#define NN  100000
#define NE  1600000
#define DD  128
#define NG  64
#define PHH 32

// ---------------- device scratch (no allocations allowed) ----------------
__device__ int   g_deg[NN];
__device__ int   g_off[NN + 1];
__device__ int   g_fill[NN];
__device__ int   g_csr[NE];
__device__ int   g_bsum[128];
__device__ int   g_boff[128];
__device__ int   g_gcnt[NG];
__device__ float g_norm[NN];
__device__ float g_pooled[NG * DD];
__device__ float g_hs[NN * DD];   // 51.2 MB
__device__ float g_x1[NN * DD];   // 51.2 MB

// ---------------- setup kernels ----------------
__global__ void k_zero() {
    int i = blockIdx.x * blockDim.x + threadIdx.x;
    if (i < NN) { g_deg[i] = 0; g_fill[i] = 0; }
    if (i < NG * DD) g_pooled[i] = 0.f;
    if (i < NG) g_gcnt[i] = 0;
}

__global__ void k_count(const int* __restrict__ dst) {
    int i = blockIdx.x * blockDim.x + threadIdx.x;
    if (i < NE) atomicAdd(&g_deg[dst[i]], 1);
}

// block-wise inclusive scan -> exclusive offsets, one block = 1024 elems
__global__ void k_scan1() {
    __shared__ int s[1024];
    int i = blockIdx.x * 1024 + threadIdx.x;
    int v = (i < NN) ? g_deg[i] : 0;
    s[threadIdx.x] = v;
    __syncthreads();
    #pragma unroll
    for (int off = 1; off < 1024; off <<= 1) {
        int t = (threadIdx.x >= off) ? s[threadIdx.x - off] : 0;
        __syncthreads();
        s[threadIdx.x] += t;
        __syncthreads();
    }
    if (i < NN) g_off[i] = s[threadIdx.x] - v;
    if (threadIdx.x == 1023) g_bsum[blockIdx.x] = s[1023];
}

__global__ void k_scan2() {   // scan 98 block sums (1 block, 128 threads)
    __shared__ int s[128];
    int t = threadIdx.x;
    int v = (t < 98) ? g_bsum[t] : 0;
    s[t] = v;
    __syncthreads();
    #pragma unroll
    for (int off = 1; off < 128; off <<= 1) {
        int x = (t >= off) ? s[t - off] : 0;
        __syncthreads();
        s[t] += x;
        __syncthreads();
    }
    g_boff[t] = s[t] - v;
}

__global__ void k_scan3(const int* __restrict__ gids) {
    int i = blockIdx.x * blockDim.x + threadIdx.x;
    if (i < NN) {
        g_off[i] += g_boff[i >> 10];
        g_norm[i] = rsqrtf((float)(g_deg[i] + 1));   // +1 = self loop
        atomicAdd(&g_gcnt[gids[i]], 1);
    }
    if (i == 0) g_off[NN] = NE;
}

__global__ void k_fill(const int* __restrict__ src, const int* __restrict__ dst) {
    int i = blockIdx.x * blockDim.x + threadIdx.x;
    if (i < NE) {
        int d = dst[i];
        int p = g_off[d] + atomicAdd(&g_fill[d], 1);
        g_csr[p] = src[i];
    }
}

// ---------------- SpMM: out = 0.5 * norm ⊙ (A_sl (norm ⊙ in)), warp/node --
__global__ void k_spmm(const float* __restrict__ fin, float* __restrict__ fout) {
    int gt = blockIdx.x * blockDim.x + threadIdx.x;
    int node = gt >> 5, lane = gt & 31;
    if (node >= NN) return;
    float nrm = g_norm[node];
    const float4* F = (const float4*)fin;
    float4 a = __ldg(F + node * 32 + lane);             // self loop
    float4 acc = make_float4(a.x * nrm, a.y * nrm, a.z * nrm, a.w * nrm);
    int beg = g_off[node], end = g_off[node + 1];
    for (int e = beg; e < end; e++) {
        int s = g_csr[e];
        float ns = g_norm[s];
        float4 v = __ldg(F + s * 32 + lane);
        acc.x = fmaf(ns, v.x, acc.x);
        acc.y = fmaf(ns, v.y, acc.y);
        acc.z = fmaf(ns, v.z, acc.z);
        acc.w = fmaf(ns, v.w, acc.w);
    }
    float sc = 0.5f * nrm;                              // fold hs = 0.5*h
    float4 o = make_float4(acc.x * sc, acc.y * sc, acc.z * sc, acc.w * sc);
    ((float4*)fout)[node * 32 + lane] = o;
}

// ---- fused GCNII GEMM: out = relu((1-b)(hs+.5 f0) + b(hs@w1 + .5 f0@w2) + bias)
// tile 64 rows x 128 cols, K=256 in four 64-chunks, 8x4 per thread.
template <bool POOL>
__global__ void __launch_bounds__(256)
k_gemm(const float* __restrict__ hs, const float* __restrict__ f0,
       const float* __restrict__ w1, const float* __restrict__ w2,
       const float* __restrict__ bias, float beta,
       float* __restrict__ xout, const int* __restrict__ gids) {
    __shared__ float As[64 * 64];   // k-major, xor-swizzled
    __shared__ float Ws[64 * 128];
    int t = threadIdx.x;
    int R0 = blockIdx.x * 64;
    int rg = t & 7;     // rows rg*8 .. rg*8+7
    int cg = t >> 3;    // cols cg*4 .. cg*4+3
    float acc[8][4];
    #pragma unroll
    for (int i = 0; i < 8; i++)
        #pragma unroll
        for (int q = 0; q < 4; q++) acc[i][q] = 0.f;

    for (int kc = 0; kc < 4; kc++) {
        const float* Wsrc = (kc < 2) ? w1 : w2;
        const float* Asrc = (kc < 2) ? hs : f0;
        float ascale = (kc < 2) ? 1.f : 0.5f;
        int kofs = (kc & 1) * 64;
        // W chunk [64][128]
        #pragma unroll
        for (int j = 0; j < 8; j++) {
            int el4 = j * 256 + t;          // float4 idx 0..2047
            int kk = el4 >> 5;
            int c4 = el4 & 31;
            float4 w = __ldg((const float4*)(Wsrc + (kofs + kk) * DD) + c4);
            ((float4*)Ws)[el4] = w;
        }
        // A chunk transposed into As[k][r] with xor swizzle on r bits 3..5
        #pragma unroll
        for (int j = 0; j < 4; j++) {
            int idx = j * 256 + t;          // 0..1023
            int r = idx >> 4;
            int k4 = idx & 15;
            int row = R0 + r;
            float4 a = make_float4(0.f, 0.f, 0.f, 0.f);
            if (row < NN) a = __ldg((const float4*)(Asrc + row * DD + kofs) + k4);
            a.x *= ascale; a.y *= ascale; a.z *= ascale; a.w *= ascale;
            float av[4] = {a.x, a.y, a.z, a.w};
            int kb = k4 * 4;
            #pragma unroll
            for (int q = 0; q < 4; q++) {
                int k = kb + q;
                int xr = r ^ (((k >> 2) & 7) << 3);
                As[k * 64 + xr] = av[q];
            }
        }
        __syncthreads();
        #pragma unroll
        for (int k = 0; k < 64; k++) {
            int xo = ((k >> 2) & 7) << 3;
            const float4* ap = (const float4*)&As[k * 64 + ((rg * 8) ^ xo)];
            float4 a0 = ap[0], a1 = ap[1];
            float4 w = *(const float4*)&Ws[k * DD + cg * 4];
            float av[8] = {a0.x, a0.y, a0.z, a0.w, a1.x, a1.y, a1.z, a1.w};
            #pragma unroll
            for (int i = 0; i < 8; i++) {
                acc[i][0] = fmaf(av[i], w.x, acc[i][0]);
                acc[i][1] = fmaf(av[i], w.y, acc[i][1]);
                acc[i][2] = fmaf(av[i], w.z, acc[i][2]);
                acc[i][3] = fmaf(av[i], w.w, acc[i][3]);
            }
        }
        __syncthreads();
    }

    float4 b4 = __ldg((const float4*)bias + cg);
    float omb = 1.f - beta;

    if (!POOL) {
        #pragma unroll
        for (int j = 0; j < 8; j++) {
            int row = R0 + rg * 8 + j;
            if (row >= NN) continue;
            float4 hv = __ldg((const float4*)(hs + row * DD) + cg);
            float4 fv = __ldg((const float4*)(f0 + row * DD) + cg);
            float4 o;
            o.x = fmaxf(fmaf(beta, acc[j][0], omb * (hv.x + 0.5f * fv.x)) + b4.x, 0.f);
            o.y = fmaxf(fmaf(beta, acc[j][1], omb * (hv.y + 0.5f * fv.y)) + b4.y, 0.f);
            o.z = fmaxf(fmaf(beta, acc[j][2], omb * (hv.z + 0.5f * fv.z)) + b4.z, 0.f);
            o.w = fmaxf(fmaf(beta, acc[j][3], omb * (hv.w + 0.5f * fv.w)) + b4.w, 0.f);
            ((float4*)(xout + row * DD))[cg] = o;
        }
    } else {
        // fused pooling: rows are consecutive & graph_ids sorted -> run-compress
        int curg = -1;
        float s0 = 0.f, s1 = 0.f, s2 = 0.f, s3 = 0.f;
        #pragma unroll
        for (int j = 0; j < 8; j++) {
            int row = R0 + rg * 8 + j;
            if (row >= NN) break;
            float4 hv = __ldg((const float4*)(hs + row * DD) + cg);
            float4 fv = __ldg((const float4*)(f0 + row * DD) + cg);
            float o0 = fmaxf(fmaf(beta, acc[j][0], omb * (hv.x + 0.5f * fv.x)) + b4.x, 0.f);
            float o1 = fmaxf(fmaf(beta, acc[j][1], omb * (hv.y + 0.5f * fv.y)) + b4.y, 0.f);
            float o2 = fmaxf(fmaf(beta, acc[j][2], omb * (hv.z + 0.5f * fv.z)) + b4.z, 0.f);
            float o3 = fmaxf(fmaf(beta, acc[j][3], omb * (hv.w + 0.5f * fv.w)) + b4.w, 0.f);
            int g = __ldg(gids + row);
            if (g != curg) {
                if (curg >= 0) {
                    atomicAdd(&g_pooled[curg * DD + cg * 4 + 0], s0);
                    atomicAdd(&g_pooled[curg * DD + cg * 4 + 1], s1);
                    atomicAdd(&g_pooled[curg * DD + cg * 4 + 2], s2);
                    atomicAdd(&g_pooled[curg * DD + cg * 4 + 3], s3);
                }
                curg = g; s0 = s1 = s2 = s3 = 0.f;
            }
            s0 += o0; s1 += o1; s2 += o2; s3 += o3;
        }
        if (curg >= 0) {
            atomicAdd(&g_pooled[curg * DD + cg * 4 + 0], s0);
            atomicAdd(&g_pooled[curg * DD + cg * 4 + 1], s1);
            atomicAdd(&g_pooled[curg * DD + cg * 4 + 2], s2);
            atomicAdd(&g_pooled[curg * DD + cg * 4 + 3], s3);
        }
    }
}

// ---------------- final MLP: [64,128] -> relu(32) -> sigmoid(1) ----------
__global__ void k_mlp(const float* __restrict__ d1w, const float* __restrict__ d1b,
                      const float* __restrict__ d2w, const float* __restrict__ d2b,
                      float* __restrict__ out) {
    int b = threadIdx.x;
    if (b >= NG) return;
    float inv = 1.f / fmaxf((float)g_gcnt[b], 1.f);
    float h[PHH];
    #pragma unroll
    for (int p = 0; p < PHH; p++) h[p] = __ldg(d1b + p);
    for (int c = 0; c < DD; c++) {
        float a = g_pooled[b * DD + c] * inv;
        #pragma unroll
        for (int p = 0; p < PHH; p++)
            h[p] = fmaf(a, __ldg(d1w + c * PHH + p), h[p]);
    }
    float z = __ldg(d2b);
    #pragma unroll
    for (int p = 0; p < PHH; p++)
        z = fmaf(fmaxf(h[p], 0.f), __ldg(d2w + p), z);
    out[b] = 1.f / (1.f + expf(-z));
}

// ---------------- launch ----------------
extern "C" void kernel_launch(void* const* d_in, const int* in_sizes, int n_in,
                              void* d_out, int out_size) {
    const float* feature = (const float*)d_in[0];
    const int*   src     = (const int*)d_in[1];
    const int*   dst     = (const int*)d_in[2];
    const int*   gids    = (const int*)d_in[3];
    const float* w1_1    = (const float*)d_in[4];
    const float* w2_1    = (const float*)d_in[5];
    const float* b_1     = (const float*)d_in[6];
    const float* w1_2    = (const float*)d_in[7];
    const float* w2_2    = (const float*)d_in[8];
    const float* b_2     = (const float*)d_in[9];
    const float* d1w     = (const float*)d_in[10];
    const float* d1b     = (const float*)d_in[11];
    const float* d2w     = (const float*)d_in[12];
    const float* d2b     = (const float*)d_in[13];
    float* out = (float*)d_out;

    const float BETA1 = 0.6931471805599453f;  // log(2)
    const float BETA2 = 0.4054651081081644f;  // log(1.5)

    float *hs_p = nullptr, *x1_p = nullptr;
    cudaGetSymbolAddress((void**)&hs_p, g_hs);
    cudaGetSymbolAddress((void**)&x1_p, g_x1);

    k_zero<<<(NN + 255) / 256, 256>>>();
    k_count<<<(NE + 255) / 256, 256>>>(dst);
    k_scan1<<<98, 1024>>>();
    k_scan2<<<1, 128>>>();
    k_scan3<<<(NN + 255) / 256, 256>>>(gids);
    k_fill<<<(NE + 255) / 256, 256>>>(src, dst);

    // layer 1
    k_spmm<<<(NN * 32 + 255) / 256, 256>>>(feature, hs_p);
    k_gemm<false><<<(NN + 63) / 64, 256>>>(hs_p, feature, w1_1, w2_1, b_1, BETA1, x1_p, nullptr);
    // layer 2 (+ fused pooling)
    k_spmm<<<(NN * 32 + 255) / 256, 256>>>(x1_p, hs_p);
    k_gemm<true><<<(NN + 63) / 64, 256>>>(hs_p, feature, w1_2, w2_2, b_2, BETA2, nullptr, gids);
    // decoder
    k_mlp<<<1, 64>>>(d1w, d1b, d2w, d2b, out);
}

// round 3
// speedup vs baseline: 1.9040x; 1.9040x over previous
#include <cuda_runtime.h>
#include <math.h>
#include <stdint.h>

#define NN  100000
#define NE  1600000
#define DD  128
#define NG  64
#define PHH 32
#define NTILES 782   // ceil(NN/128)

// ---------------- device scratch (no allocations allowed) ----------------
__device__ int   g_deg[NN];
__device__ int   g_off[NN + 1];
__device__ int   g_fill[NN];
__device__ int   g_csr[NE];
__device__ int   g_bsum[128];
__device__ int   g_boff[128];
__device__ int   g_gcnt[NG];
__device__ float g_norm[NN];
__device__ float g_pooled[NG * DD];
__device__ float g_hs[NN * DD];        // 51.2 MB, tf32-rounded spmm output
__device__ float g_x1[NN * DD];        // 51.2 MB, layer outputs
__device__ float g_ft[NN * DD];        // 51.2 MB, tf32-rounded feature
__device__ float g_w1e[2][DD * DD];    // effective W1 per layer, [n][k], tf32
__device__ float g_w2e[2][DD * DD];    // effective W2 per layer (x0.5), [n][k], tf32

// ---------------- helpers ----------------
__device__ __forceinline__ uint32_t smem_u32(const void* p) {
    uint32_t a;
    asm("{ .reg .u64 t; cvta.to.shared.u64 t, %1; cvt.u32.u64 %0, t; }"
        : "=r"(a) : "l"(p));
    return a;
}

__device__ __forceinline__ float tf32r(float x) {
    uint32_t u;
    asm("cvt.rna.tf32.f32 %0, %1;" : "=r"(u) : "f"(x));
    return __uint_as_float(u);
}

__device__ __forceinline__ void cpa16(uint32_t dst, const float* src) {
    asm volatile("cp.async.cg.shared.global [%0], [%1], 16;"
                 :: "r"(dst), "l"(src) : "memory");
}

__device__ __forceinline__ void ldsm4(uint32_t* r, uint32_t addr) {
    asm volatile("ldmatrix.sync.aligned.m8n8.x4.shared.b16 {%0,%1,%2,%3}, [%4];"
                 : "=r"(r[0]), "=r"(r[1]), "=r"(r[2]), "=r"(r[3]) : "r"(addr));
}

__device__ __forceinline__ void mma8(float* c, const uint32_t* a,
                                     uint32_t b0, uint32_t b1) {
    asm volatile(
        "mma.sync.aligned.m16n8k8.row.col.f32.tf32.tf32.f32 "
        "{%0,%1,%2,%3}, {%4,%5,%6,%7}, {%8,%9}, {%0,%1,%2,%3};"
        : "+f"(c[0]), "+f"(c[1]), "+f"(c[2]), "+f"(c[3])
        : "r"(a[0]), "r"(a[1]), "r"(a[2]), "r"(a[3]), "r"(b0), "r"(b1));
}

// ---------------- setup kernels ----------------
__global__ void k_zero() {
    int i = blockIdx.x * blockDim.x + threadIdx.x;
    if (i < NN) { g_deg[i] = 0; g_fill[i] = 0; }
    if (i < NG * DD) g_pooled[i] = 0.f;
    if (i < NG) g_gcnt[i] = 0;
}

__global__ void k_count(const int* __restrict__ dst) {
    int i = blockIdx.x * blockDim.x + threadIdx.x;
    if (i < NE) atomicAdd(&g_deg[dst[i]], 1);
}

__global__ void k_scan1() {
    __shared__ int s[1024];
    int i = blockIdx.x * 1024 + threadIdx.x;
    int v = (i < NN) ? g_deg[i] : 0;
    s[threadIdx.x] = v;
    __syncthreads();
    #pragma unroll
    for (int off = 1; off < 1024; off <<= 1) {
        int t = (threadIdx.x >= off) ? s[threadIdx.x - off] : 0;
        __syncthreads();
        s[threadIdx.x] += t;
        __syncthreads();
    }
    if (i < NN) g_off[i] = s[threadIdx.x] - v;
    if (threadIdx.x == 1023) g_bsum[blockIdx.x] = s[1023];
}

__global__ void k_scan2() {
    __shared__ int s[128];
    int t = threadIdx.x;
    int v = (t < 98) ? g_bsum[t] : 0;
    s[t] = v;
    __syncthreads();
    #pragma unroll
    for (int off = 1; off < 128; off <<= 1) {
        int x = (t >= off) ? s[t - off] : 0;
        __syncthreads();
        s[t] += x;
        __syncthreads();
    }
    g_boff[t] = s[t] - v;
}

__global__ void k_scan3(const int* __restrict__ gids) {
    int i = blockIdx.x * blockDim.x + threadIdx.x;
    if (i < NN) {
        g_off[i] += g_boff[i >> 10];
        g_norm[i] = rsqrtf((float)(g_deg[i] + 1));
        atomicAdd(&g_gcnt[gids[i]], 1);
    }
    if (i == 0) g_off[NN] = NE;
}

__global__ void k_fill(const int* __restrict__ src, const int* __restrict__ dst) {
    int i = blockIdx.x * blockDim.x + threadIdx.x;
    if (i < NE) {
        int d = dst[i];
        int p = g_off[d] + atomicAdd(&g_fill[d], 1);
        g_csr[p] = src[i];
    }
}

// effective weights, transposed to [n][k], tf32-rounded:
//   W1e = (1-b) I + b w1 ;  W2e = 0.5((1-b) I + b w2)
__global__ void k_prep(const float* __restrict__ w11, const float* __restrict__ w21,
                       const float* __restrict__ w12, const float* __restrict__ w22) {
    int n = blockIdx.x, k = threadIdx.x;
    const float B1 = 0.6931471805599453f;  // log 2
    const float B2 = 0.4054651081081644f;  // log 1.5
    float ikn = (k == n) ? 1.f : 0.f;
    g_w1e[0][n * DD + k] = tf32r(B1 * w11[k * DD + n] + (1.f - B1) * ikn);
    g_w2e[0][n * DD + k] = tf32r(0.5f * (B1 * w21[k * DD + n] + (1.f - B1) * ikn));
    g_w1e[1][n * DD + k] = tf32r(B2 * w12[k * DD + n] + (1.f - B2) * ikn);
    g_w2e[1][n * DD + k] = tf32r(0.5f * (B2 * w22[k * DD + n] + (1.f - B2) * ikn));
}

// rounded copy of feature (GEMM f0 operand)
__global__ void k_round(const float* __restrict__ fin) {
    int i = blockIdx.x * blockDim.x + threadIdx.x;
    if (i < NN * DD / 4) {
        float4 v = __ldg((const float4*)fin + i);
        v.x = tf32r(v.x); v.y = tf32r(v.y); v.z = tf32r(v.z); v.w = tf32r(v.w);
        ((float4*)g_ft)[i] = v;
    }
}

// ---------------- SpMM: out = tf32(0.5 * norm ⊙ (A_sl (norm ⊙ in))) --------
__global__ void k_spmm(const float* __restrict__ fin, float* __restrict__ fout) {
    int gt = blockIdx.x * blockDim.x + threadIdx.x;
    int node = gt >> 5, lane = gt & 31;
    if (node >= NN) return;
    float nrm = g_norm[node];
    const float4* F = (const float4*)fin;
    float4 a = __ldg(F + node * 32 + lane);
    float4 acc = make_float4(a.x * nrm, a.y * nrm, a.z * nrm, a.w * nrm);
    int beg = g_off[node], end = g_off[node + 1];
    for (int e = beg; e < end; e++) {
        int s = g_csr[e];
        float ns = g_norm[s];
        float4 v = __ldg(F + s * 32 + lane);
        acc.x = fmaf(ns, v.x, acc.x);
        acc.y = fmaf(ns, v.y, acc.y);
        acc.z = fmaf(ns, v.z, acc.z);
        acc.w = fmaf(ns, v.w, acc.w);
    }
    float sc = 0.5f * nrm;
    ((float4*)fout)[node * 32 + lane] =
        make_float4(tf32r(acc.x * sc), tf32r(acc.y * sc),
                    tf32r(acc.z * sc), tf32r(acc.w * sc));
}

// ---- tf32 mma.sync GEMM: out = relu(hs@W1e + f0@W2e + b) ------------------
// BM=128, BN=128, K=256 (hs|f0), BK=32, 8 warps (warp tile 32x64),
// 2-stage cp.async pipeline, SW128 swizzle, ldmatrix fragments.
__global__ void __launch_bounds__(256, 2)
k_mma(const float* __restrict__ Ahs, const float* __restrict__ Af0,
      const float* __restrict__ Bw1, const float* __restrict__ Bw2,
      const float* __restrict__ bias, float* __restrict__ xout) {
    extern __shared__ float smem[];   // 2 stages x (A 16KB + B 16KB)
    uint32_t sb = smem_u32(smem);
    int t = threadIdx.x, lane = t & 31, w = t >> 5;
    int wm = (w & 3) * 32, wn = (w >> 2) * 64;
    int R0 = blockIdx.x * 128;

    float acc[2][8][4];
    #pragma unroll
    for (int mt = 0; mt < 2; mt++)
        #pragma unroll
        for (int j = 0; j < 8; j++)
            #pragma unroll
            for (int q = 0; q < 4; q++) acc[mt][j][q] = 0.f;

    auto load_chunk = [&](int c) {
        int s = c & 1;
        uint32_t aB = sb + s * 32768;
        uint32_t bB = aB + 16384;
        const float* A = (c < 4) ? Ahs : Af0;
        const float* B = (c < 4) ? Bw1 : Bw2;
        int ko = (c & 3) * 32;
        #pragma unroll
        for (int i = 0; i < 4; i++) {
            int idx = i * 256 + t;            // 0..1023
            int r = idx >> 3, f4 = idx & 7;
            int row = R0 + r; if (row >= NN) row = 0;
            uint32_t off = r * 128 + ((f4 * 16) ^ ((r & 7) << 4));
            cpa16(aB + off, A + (size_t)row * DD + ko + f4 * 4);
            cpa16(bB + off, B + (size_t)r * DD + ko + f4 * 4);
        }
        asm volatile("cp.async.commit_group;" ::: "memory");
    };

    load_chunk(0);
    load_chunk(1);

    // per-lane ldmatrix row indices (within 128-row tile) and swizzles
    int rA[2], rB[4];
    #pragma unroll
    for (int mt = 0; mt < 2; mt++)
        rA[mt] = wm + mt * 16 + (lane & 7) + ((lane >> 3) & 1) * 8;
    #pragma unroll
    for (int nt = 0; nt < 4; nt++)
        rB[nt] = wn + nt * 16 + (lane & 7) + ((lane >> 4) & 1) * 8;
    uint32_t aH = ((lane >> 4) & 1) * 16;   // A: k-half from bit4
    uint32_t bH = ((lane >> 3) & 1) * 16;   // B: k-half from bit3

    for (int c = 0; c < 8; c++) {
        int s = c & 1;
        if (c < 7) asm volatile("cp.async.wait_group 1;" ::: "memory");
        else       asm volatile("cp.async.wait_group 0;" ::: "memory");
        __syncthreads();

        uint32_t aB = sb + s * 32768;
        uint32_t bB = aB + 16384;
        #pragma unroll
        for (int kk = 0; kk < 4; kk++) {
            uint32_t a[2][4], b[4][4];
            #pragma unroll
            for (int mt = 0; mt < 2; mt++)
                ldsm4(a[mt], aB + rA[mt] * 128 +
                              (((uint32_t)(kk * 32) + aH) ^ ((rA[mt] & 7) << 4)));
            #pragma unroll
            for (int nt = 0; nt < 4; nt++)
                ldsm4(b[nt], bB + rB[nt] * 128 +
                              (((uint32_t)(kk * 32) + bH) ^ ((rB[nt] & 7) << 4)));
            #pragma unroll
            for (int mt = 0; mt < 2; mt++)
                #pragma unroll
                for (int nt = 0; nt < 4; nt++) {
                    mma8(acc[mt][2 * nt + 0], a[mt], b[nt][0], b[nt][1]);
                    mma8(acc[mt][2 * nt + 1], a[mt], b[nt][2], b[nt][3]);
                }
        }
        __syncthreads();
        if (c + 2 < 8) load_chunk(c + 2);
    }

    // epilogue: bias + relu
    #pragma unroll
    for (int mt = 0; mt < 2; mt++) {
        int row0 = R0 + wm + mt * 16 + (lane >> 2);
        #pragma unroll
        for (int j = 0; j < 8; j++) {
            int col = wn + j * 8 + (lane & 3) * 2;
            float2 bb = *(const float2*)(bias + col);
            if (row0 < NN) {
                float2 v;
                v.x = fmaxf(acc[mt][j][0] + bb.x, 0.f);
                v.y = fmaxf(acc[mt][j][1] + bb.y, 0.f);
                *(float2*)(xout + (size_t)row0 * DD + col) = v;
            }
            if (row0 + 8 < NN) {
                float2 v;
                v.x = fmaxf(acc[mt][j][2] + bb.x, 0.f);
                v.y = fmaxf(acc[mt][j][3] + bb.y, 0.f);
                *(float2*)(xout + (size_t)(row0 + 8) * DD + col) = v;
            }
        }
    }
}

// ---------------- pooling: segmented sum over sorted graph_ids -------------
__global__ void k_pool(const float* __restrict__ x2, const int* __restrict__ gids) {
    int c  = threadIdx.x;             // 128 cols
    int r0 = blockIdx.x * 128;
    int re = min(r0 + 128, NN);
    int curg = -1;
    float s = 0.f;
    for (int r = r0; r < re; r++) {
        int g = __ldg(gids + r);
        float v = __ldg(x2 + (size_t)r * DD + c);
        if (g != curg) {
            if (curg >= 0) atomicAdd(&g_pooled[curg * DD + c], s);
            curg = g; s = 0.f;
        }
        s += v;
    }
    if (curg >= 0) atomicAdd(&g_pooled[curg * DD + c], s);
}

// ---------------- final MLP ----------------
__global__ void k_mlp(const float* __restrict__ d1w, const float* __restrict__ d1b,
                      const float* __restrict__ d2w, const float* __restrict__ d2b,
                      float* __restrict__ out) {
    int b = threadIdx.x;
    if (b >= NG) return;
    float inv = 1.f / fmaxf((float)g_gcnt[b], 1.f);
    float h[PHH];
    #pragma unroll
    for (int p = 0; p < PHH; p++) h[p] = __ldg(d1b + p);
    for (int c = 0; c < DD; c++) {
        float a = g_pooled[b * DD + c] * inv;
        #pragma unroll
        for (int p = 0; p < PHH; p++)
            h[p] = fmaf(a, __ldg(d1w + c * PHH + p), h[p]);
    }
    float z = __ldg(d2b);
    #pragma unroll
    for (int p = 0; p < PHH; p++)
        z = fmaf(fmaxf(h[p], 0.f), __ldg(d2w + p), z);
    out[b] = 1.f / (1.f + expf(-z));
}

// ---------------- launch ----------------
extern "C" void kernel_launch(void* const* d_in, const int* in_sizes, int n_in,
                              void* d_out, int out_size) {
    const float* feature = (const float*)d_in[0];
    const int*   src     = (const int*)d_in[1];
    const int*   dst     = (const int*)d_in[2];
    const int*   gids    = (const int*)d_in[3];
    const float* w1_1    = (const float*)d_in[4];
    const float* w2_1    = (const float*)d_in[5];
    const float* b_1     = (const float*)d_in[6];
    const float* w1_2    = (const float*)d_in[7];
    const float* w2_2    = (const float*)d_in[8];
    const float* b_2     = (const float*)d_in[9];
    const float* d1w     = (const float*)d_in[10];
    const float* d1b     = (const float*)d_in[11];
    const float* d2w     = (const float*)d_in[12];
    const float* d2b     = (const float*)d_in[13];
    float* out = (float*)d_out;

    float *hs_p = nullptr, *x1_p = nullptr, *ft_p = nullptr;
    float *w1e_p = nullptr, *w2e_p = nullptr;
    cudaGetSymbolAddress((void**)&hs_p,  g_hs);
    cudaGetSymbolAddress((void**)&x1_p,  g_x1);
    cudaGetSymbolAddress((void**)&ft_p,  g_ft);
    cudaGetSymbolAddress((void**)&w1e_p, g_w1e);
    cudaGetSymbolAddress((void**)&w2e_p, g_w2e);

    const int SMEM_MMA = 65536;   // 2 stages x (A 16KB + B 16KB)
    cudaFuncSetAttribute(k_mma, cudaFuncAttributeMaxDynamicSharedMemorySize, SMEM_MMA);

    k_zero<<<(NN + 255) / 256, 256>>>();
    k_count<<<(NE + 255) / 256, 256>>>(dst);
    k_scan1<<<98, 1024>>>();
    k_scan2<<<1, 128>>>();
    k_scan3<<<(NN + 255) / 256, 256>>>(gids);
    k_fill<<<(NE + 255) / 256, 256>>>(src, dst);
    k_prep<<<DD, DD>>>(w1_1, w2_1, w1_2, w2_2);
    k_round<<<(NN * DD / 4 + 255) / 256, 256>>>(feature);

    // layer 1
    k_spmm<<<(NN * 32 + 255) / 256, 256>>>(feature, hs_p);
    k_mma<<<NTILES, 256, SMEM_MMA>>>(hs_p, ft_p, w1e_p, w2e_p, b_1, x1_p);
    // layer 2
    k_spmm<<<(NN * 32 + 255) / 256, 256>>>(x1_p, hs_p);
    k_mma<<<NTILES, 256, SMEM_MMA>>>(hs_p, ft_p,
                                     w1e_p + DD * DD, w2e_p + DD * DD, b_2, x1_p);
    // pooling + decoder
    k_pool<<<NTILES, 128>>>(x1_p, gids);
    k_mlp<<<1, 64>>>(d1w, d1b, d2w, d2b, out);
}

// round 4
// speedup vs baseline: 2.0086x; 1.0550x over previous
#include <cuda_runtime.h>
#include <cuda_bf16.h>
#include <math.h>
#include <stdint.h>

#define NN  100000
#define NE  1600000
#define DD  128
#define NG  64
#define PHH 32
#define NTILES 782   // ceil(NN/128)

// ---------------- device scratch (no allocations allowed) ----------------
__device__ int   g_deg[NN];
__device__ int   g_off[NN + 1];
__device__ int   g_fill[NN];
__device__ int   g_csr[NE];
__device__ int   g_bsum[128];
__device__ int   g_boff[128];
__device__ int   g_gcnt[NG];
__device__ float g_norm[NN];
__device__ float g_pooled[NG * DD];
__device__ float g_hs[NN * DD];             // spmm output (tf32-rounded)
__device__ float g_x1[NN * DD];             // layer-2 output (fp32, for pooling)
__device__ float g_ft[NN * DD];             // tf32-rounded feature (GEMM f0)
__device__ uint16_t g_fb[NN * DD];          // bf16 feature (spmm L1 gather), 25.6MB
__device__ uint16_t g_xb[NN * DD];          // bf16 x1 (spmm L2 gather), 25.6MB
__device__ float g_w1e[2][DD * DD];         // effective W1, [n][k], tf32
__device__ float g_w2e[2][DD * DD];         // effective W2 (x0.5), [n][k], tf32

// ---------------- helpers ----------------
__device__ __forceinline__ uint32_t smem_u32(const void* p) {
    uint32_t a;
    asm("{ .reg .u64 t; cvta.to.shared.u64 t, %1; cvt.u32.u64 %0, t; }"
        : "=r"(a) : "l"(p));
    return a;
}

__device__ __forceinline__ float tf32r(float x) {
    uint32_t u;
    asm("cvt.rna.tf32.f32 %0, %1;" : "=r"(u) : "f"(x));
    return __uint_as_float(u);
}

__device__ __forceinline__ uint32_t bf2pack(float lo, float hi) {
    uint32_t p;
    asm("cvt.rn.bf16x2.f32 %0, %1, %2;" : "=r"(p) : "f"(hi), "f"(lo));
    return p;
}

__device__ __forceinline__ void cpa16(uint32_t dst, const float* src) {
    asm volatile("cp.async.cg.shared.global [%0], [%1], 16;"
                 :: "r"(dst), "l"(src) : "memory");
}

__device__ __forceinline__ void ldsm4(uint32_t* r, uint32_t addr) {
    asm volatile("ldmatrix.sync.aligned.m8n8.x4.shared.b16 {%0,%1,%2,%3}, [%4];"
                 : "=r"(r[0]), "=r"(r[1]), "=r"(r[2]), "=r"(r[3]) : "r"(addr));
}

__device__ __forceinline__ void mma8(float* c, const uint32_t* a,
                                     uint32_t b0, uint32_t b1) {
    asm volatile(
        "mma.sync.aligned.m16n8k8.row.col.f32.tf32.tf32.f32 "
        "{%0,%1,%2,%3}, {%4,%5,%6,%7}, {%8,%9}, {%0,%1,%2,%3};"
        : "+f"(c[0]), "+f"(c[1]), "+f"(c[2]), "+f"(c[3])
        : "r"(a[0]), "r"(a[1]), "r"(a[2]), "r"(a[3]), "r"(b0), "r"(b1));
}

// unpack 2 bf16 from u32 (elem0 = low 16 bits)
__device__ __forceinline__ float bflo(uint32_t u) { return __uint_as_float(u << 16); }
__device__ __forceinline__ float bfhi(uint32_t u) { return __uint_as_float(u & 0xFFFF0000u); }

// ---------------- setup kernels ----------------
__global__ void k_zero() {
    int i = blockIdx.x * blockDim.x + threadIdx.x;
    if (i < NN) { g_deg[i] = 0; g_fill[i] = 0; }
    if (i < NG * DD) g_pooled[i] = 0.f;
    if (i < NG) g_gcnt[i] = 0;
}

__global__ void k_count(const int* __restrict__ dst) {
    int i = blockIdx.x * blockDim.x + threadIdx.x;
    if (i < NE) atomicAdd(&g_deg[dst[i]], 1);
}

__global__ void k_scan1() {
    __shared__ int s[1024];
    int i = blockIdx.x * 1024 + threadIdx.x;
    int v = (i < NN) ? g_deg[i] : 0;
    s[threadIdx.x] = v;
    __syncthreads();
    #pragma unroll
    for (int off = 1; off < 1024; off <<= 1) {
        int t = (threadIdx.x >= off) ? s[threadIdx.x - off] : 0;
        __syncthreads();
        s[threadIdx.x] += t;
        __syncthreads();
    }
    if (i < NN) g_off[i] = s[threadIdx.x] - v;
    if (threadIdx.x == 1023) g_bsum[blockIdx.x] = s[1023];
}

__global__ void k_scan2() {
    __shared__ int s[128];
    int t = threadIdx.x;
    int v = (t < 98) ? g_bsum[t] : 0;
    s[t] = v;
    __syncthreads();
    #pragma unroll
    for (int off = 1; off < 128; off <<= 1) {
        int x = (t >= off) ? s[t - off] : 0;
        __syncthreads();
        s[t] += x;
        __syncthreads();
    }
    g_boff[t] = s[t] - v;
}

__global__ void k_scan3(const int* __restrict__ gids) {
    int i = blockIdx.x * blockDim.x + threadIdx.x;
    if (i < NN) {
        g_off[i] += g_boff[i >> 10];
        g_norm[i] = rsqrtf((float)(g_deg[i] + 1));
        atomicAdd(&g_gcnt[gids[i]], 1);
    }
    if (i == 0) g_off[NN] = NE;
}

__global__ void k_fill(const int* __restrict__ src, const int* __restrict__ dst) {
    int i = blockIdx.x * blockDim.x + threadIdx.x;
    if (i < NE) {
        int d = dst[i];
        int p = g_off[d] + atomicAdd(&g_fill[d], 1);
        g_csr[p] = src[i];
    }
}

// effective weights, transposed to [n][k], tf32-rounded:
//   W1e = (1-b) I + b w1 ;  W2e = 0.5((1-b) I + b w2)
__global__ void k_prep(const float* __restrict__ w11, const float* __restrict__ w21,
                       const float* __restrict__ w12, const float* __restrict__ w22) {
    int n = blockIdx.x, k = threadIdx.x;
    const float B1 = 0.6931471805599453f;  // log 2
    const float B2 = 0.4054651081081644f;  // log 1.5
    float ikn = (k == n) ? 1.f : 0.f;
    g_w1e[0][n * DD + k] = tf32r(B1 * w11[k * DD + n] + (1.f - B1) * ikn);
    g_w2e[0][n * DD + k] = tf32r(0.5f * (B1 * w21[k * DD + n] + (1.f - B1) * ikn));
    g_w1e[1][n * DD + k] = tf32r(B2 * w12[k * DD + n] + (1.f - B2) * ikn);
    g_w2e[1][n * DD + k] = tf32r(0.5f * (B2 * w22[k * DD + n] + (1.f - B2) * ikn));
}

// rounded copies of feature: tf32 (GEMM f0 operand) + bf16 (spmm gather)
__global__ void k_round(const float* __restrict__ fin) {
    int i = blockIdx.x * blockDim.x + threadIdx.x;
    if (i < NN * DD / 4) {
        float4 v = __ldg((const float4*)fin + i);
        float4 o = make_float4(tf32r(v.x), tf32r(v.y), tf32r(v.z), tf32r(v.w));
        ((float4*)g_ft)[i] = o;
        uint2 b;
        b.x = bf2pack(v.x, v.y);
        b.y = bf2pack(v.z, v.w);
        ((uint2*)g_fb)[i] = b;
    }
}

// ---- SpMM (bf16 gather): out = tf32(0.5 * norm ⊙ (A_sl (norm ⊙ in))) ------
// warp/node; lane covers 4 cols (uint2 = 4 bf16); 2-edge software pipeline.
__global__ void k_spmm(const uint16_t* __restrict__ fin, float* __restrict__ fout) {
    int gt = blockIdx.x * blockDim.x + threadIdx.x;
    int node = gt >> 5, lane = gt & 31;
    if (node >= NN) return;
    float nrm = g_norm[node];
    const uint2* F = (const uint2*)fin;
    uint2 a = __ldg(F + node * 32 + lane);   // self loop
    float4 acc;
    acc.x = bflo(a.x) * nrm; acc.y = bfhi(a.x) * nrm;
    acc.z = bflo(a.y) * nrm; acc.w = bfhi(a.y) * nrm;
    int beg = g_off[node], end = g_off[node + 1];
    int e = beg;
    for (; e + 2 <= end; e += 2) {
        int s0 = __ldg(g_csr + e), s1 = __ldg(g_csr + e + 1);
        float n0 = __ldg(g_norm + s0), n1 = __ldg(g_norm + s1);
        uint2 v0 = __ldg(F + s0 * 32 + lane);
        uint2 v1 = __ldg(F + s1 * 32 + lane);
        acc.x = fmaf(n0, bflo(v0.x), acc.x);
        acc.y = fmaf(n0, bfhi(v0.x), acc.y);
        acc.z = fmaf(n0, bflo(v0.y), acc.z);
        acc.w = fmaf(n0, bfhi(v0.y), acc.w);
        acc.x = fmaf(n1, bflo(v1.x), acc.x);
        acc.y = fmaf(n1, bfhi(v1.x), acc.y);
        acc.z = fmaf(n1, bflo(v1.y), acc.z);
        acc.w = fmaf(n1, bfhi(v1.y), acc.w);
    }
    if (e < end) {
        int s0 = __ldg(g_csr + e);
        float n0 = __ldg(g_norm + s0);
        uint2 v0 = __ldg(F + s0 * 32 + lane);
        acc.x = fmaf(n0, bflo(v0.x), acc.x);
        acc.y = fmaf(n0, bfhi(v0.x), acc.y);
        acc.z = fmaf(n0, bflo(v0.y), acc.z);
        acc.w = fmaf(n0, bfhi(v0.y), acc.w);
    }
    float sc = 0.5f * nrm;
    ((float4*)fout)[node * 32 + lane] =
        make_float4(tf32r(acc.x * sc), tf32r(acc.y * sc),
                    tf32r(acc.z * sc), tf32r(acc.w * sc));
}

// ---- tf32 mma.sync GEMM: out = relu(hs@W1e + f0@W2e + b) ------------------
// BM=128, BN=128, K=256 (hs|f0), BK=32, 8 warps (warp tile 32x64),
// 2-stage cp.async pipeline, SW128 swizzle, ldmatrix fragments.
// OUTBF=1: write bf16 (layer1, feeds spmm L2); OUTBF=0: write fp32 (layer2).
template <int OUTBF>
__global__ void __launch_bounds__(256, 2)
k_mma(const float* __restrict__ Ahs, const float* __restrict__ Af0,
      const float* __restrict__ Bw1, const float* __restrict__ Bw2,
      const float* __restrict__ bias, float* __restrict__ xout,
      uint16_t* __restrict__ xbout) {
    extern __shared__ float smem[];   // 2 stages x (A 16KB + B 16KB)
    uint32_t sb = smem_u32(smem);
    int t = threadIdx.x, lane = t & 31, w = t >> 5;
    int wm = (w & 3) * 32, wn = (w >> 2) * 64;
    int R0 = blockIdx.x * 128;

    float acc[2][8][4];
    #pragma unroll
    for (int mt = 0; mt < 2; mt++)
        #pragma unroll
        for (int j = 0; j < 8; j++)
            #pragma unroll
            for (int q = 0; q < 4; q++) acc[mt][j][q] = 0.f;

    auto load_chunk = [&](int c) {
        int s = c & 1;
        uint32_t aB = sb + s * 32768;
        uint32_t bB = aB + 16384;
        const float* A = (c < 4) ? Ahs : Af0;
        const float* B = (c < 4) ? Bw1 : Bw2;
        int ko = (c & 3) * 32;
        #pragma unroll
        for (int i = 0; i < 4; i++) {
            int idx = i * 256 + t;            // 0..1023
            int r = idx >> 3, f4 = idx & 7;
            int row = R0 + r; if (row >= NN) row = 0;
            uint32_t off = r * 128 + ((f4 * 16) ^ ((r & 7) << 4));
            cpa16(aB + off, A + (size_t)row * DD + ko + f4 * 4);
            cpa16(bB + off, B + (size_t)r * DD + ko + f4 * 4);
        }
        asm volatile("cp.async.commit_group;" ::: "memory");
    };

    load_chunk(0);
    load_chunk(1);

    int rA[2], rB[4];
    #pragma unroll
    for (int mt = 0; mt < 2; mt++)
        rA[mt] = wm + mt * 16 + (lane & 7) + ((lane >> 3) & 1) * 8;
    #pragma unroll
    for (int nt = 0; nt < 4; nt++)
        rB[nt] = wn + nt * 16 + (lane & 7) + ((lane >> 4) & 1) * 8;
    uint32_t aH = ((lane >> 4) & 1) * 16;
    uint32_t bH = ((lane >> 3) & 1) * 16;

    for (int c = 0; c < 8; c++) {
        int s = c & 1;
        if (c < 7) asm volatile("cp.async.wait_group 1;" ::: "memory");
        else       asm volatile("cp.async.wait_group 0;" ::: "memory");
        __syncthreads();

        uint32_t aB = sb + s * 32768;
        uint32_t bB = aB + 16384;
        #pragma unroll
        for (int kk = 0; kk < 4; kk++) {
            uint32_t a[2][4], b[4][4];
            #pragma unroll
            for (int mt = 0; mt < 2; mt++)
                ldsm4(a[mt], aB + rA[mt] * 128 +
                              (((uint32_t)(kk * 32) + aH) ^ ((rA[mt] & 7) << 4)));
            #pragma unroll
            for (int nt = 0; nt < 4; nt++)
                ldsm4(b[nt], bB + rB[nt] * 128 +
                              (((uint32_t)(kk * 32) + bH) ^ ((rB[nt] & 7) << 4)));
            #pragma unroll
            for (int mt = 0; mt < 2; mt++)
                #pragma unroll
                for (int nt = 0; nt < 4; nt++) {
                    mma8(acc[mt][2 * nt + 0], a[mt], b[nt][0], b[nt][1]);
                    mma8(acc[mt][2 * nt + 1], a[mt], b[nt][2], b[nt][3]);
                }
        }
        __syncthreads();
        if (c + 2 < 8) load_chunk(c + 2);
    }

    // epilogue: bias + relu (+ bf16 pack for layer 1)
    #pragma unroll
    for (int mt = 0; mt < 2; mt++) {
        int row0 = R0 + wm + mt * 16 + (lane >> 2);
        #pragma unroll
        for (int j = 0; j < 8; j++) {
            int col = wn + j * 8 + (lane & 3) * 2;
            float2 bb = *(const float2*)(bias + col);
            float v0 = fmaxf(acc[mt][j][0] + bb.x, 0.f);
            float v1 = fmaxf(acc[mt][j][1] + bb.y, 0.f);
            float v2 = fmaxf(acc[mt][j][2] + bb.x, 0.f);
            float v3 = fmaxf(acc[mt][j][3] + bb.y, 0.f);
            if (OUTBF) {
                if (row0 < NN)
                    *(uint32_t*)(xbout + (size_t)row0 * DD + col) = bf2pack(v0, v1);
                if (row0 + 8 < NN)
                    *(uint32_t*)(xbout + (size_t)(row0 + 8) * DD + col) = bf2pack(v2, v3);
            } else {
                if (row0 < NN)
                    *(float2*)(xout + (size_t)row0 * DD + col) = make_float2(v0, v1);
                if (row0 + 8 < NN)
                    *(float2*)(xout + (size_t)(row0 + 8) * DD + col) = make_float2(v2, v3);
            }
        }
    }
}

// ---------------- pooling: segmented sum over sorted graph_ids -------------
__global__ void k_pool(const float* __restrict__ x2, const int* __restrict__ gids) {
    int c  = threadIdx.x;             // 128 cols
    int r0 = blockIdx.x * 128;
    int re = min(r0 + 128, NN);
    int curg = -1;
    float s = 0.f;
    for (int r = r0; r < re; r++) {
        int g = __ldg(gids + r);
        float v = __ldg(x2 + (size_t)r * DD + c);
        if (g != curg) {
            if (curg >= 0) atomicAdd(&g_pooled[curg * DD + c], s);
            curg = g; s = 0.f;
        }
        s += v;
    }
    if (curg >= 0) atomicAdd(&g_pooled[curg * DD + c], s);
}

// ---------------- final MLP ----------------
__global__ void k_mlp(const float* __restrict__ d1w, const float* __restrict__ d1b,
                      const float* __restrict__ d2w, const float* __restrict__ d2b,
                      float* __restrict__ out) {
    int b = threadIdx.x;
    if (b >= NG) return;
    float inv = 1.f / fmaxf((float)g_gcnt[b], 1.f);
    float h[PHH];
    #pragma unroll
    for (int p = 0; p < PHH; p++) h[p] = __ldg(d1b + p);
    for (int c = 0; c < DD; c++) {
        float a = g_pooled[b * DD + c] * inv;
        #pragma unroll
        for (int p = 0; p < PHH; p++)
            h[p] = fmaf(a, __ldg(d1w + c * PHH + p), h[p]);
    }
    float z = __ldg(d2b);
    #pragma unroll
    for (int p = 0; p < PHH; p++)
        z = fmaf(fmaxf(h[p], 0.f), __ldg(d2w + p), z);
    out[b] = 1.f / (1.f + expf(-z));
}

// ---------------- launch ----------------
extern "C" void kernel_launch(void* const* d_in, const int* in_sizes, int n_in,
                              void* d_out, int out_size) {
    const float* feature = (const float*)d_in[0];
    const int*   src     = (const int*)d_in[1];
    const int*   dst     = (const int*)d_in[2];
    const int*   gids    = (const int*)d_in[3];
    const float* w1_1    = (const float*)d_in[4];
    const float* w2_1    = (const float*)d_in[5];
    const float* b_1     = (const float*)d_in[6];
    const float* w1_2    = (const float*)d_in[7];
    const float* w2_2    = (const float*)d_in[8];
    const float* b_2     = (const float*)d_in[9];
    const float* d1w     = (const float*)d_in[10];
    const float* d1b     = (const float*)d_in[11];
    const float* d2w     = (const float*)d_in[12];
    const float* d2b     = (const float*)d_in[13];
    float* out = (float*)d_out;

    float *hs_p = nullptr, *x1_p = nullptr, *ft_p = nullptr;
    float *w1e_p = nullptr, *w2e_p = nullptr;
    uint16_t *fb_p = nullptr, *xb_p = nullptr;
    cudaGetSymbolAddress((void**)&hs_p,  g_hs);
    cudaGetSymbolAddress((void**)&x1_p,  g_x1);
    cudaGetSymbolAddress((void**)&ft_p,  g_ft);
    cudaGetSymbolAddress((void**)&fb_p,  g_fb);
    cudaGetSymbolAddress((void**)&xb_p,  g_xb);
    cudaGetSymbolAddress((void**)&w1e_p, g_w1e);
    cudaGetSymbolAddress((void**)&w2e_p, g_w2e);

    const int SMEM_MMA = 65536;   // 2 stages x (A 16KB + B 16KB)
    cudaFuncSetAttribute(k_mma<0>, cudaFuncAttributeMaxDynamicSharedMemorySize, SMEM_MMA);
    cudaFuncSetAttribute(k_mma<1>, cudaFuncAttributeMaxDynamicSharedMemorySize, SMEM_MMA);

    k_zero<<<(NN + 255) / 256, 256>>>();
    k_count<<<(NE + 255) / 256, 256>>>(dst);
    k_scan1<<<98, 1024>>>();
    k_scan2<<<1, 128>>>();
    k_scan3<<<(NN + 255) / 256, 256>>>(gids);
    k_fill<<<(NE + 255) / 256, 256>>>(src, dst);
    k_prep<<<DD, DD>>>(w1_1, w2_1, w1_2, w2_2);
    k_round<<<(NN * DD / 4 + 255) / 256, 256>>>(feature);

    // layer 1 (spmm gathers bf16 feature; gemm writes bf16 x1)
    k_spmm<<<(NN * 32 + 255) / 256, 256>>>(fb_p, hs_p);
    k_mma<1><<<NTILES, 256, SMEM_MMA>>>(hs_p, ft_p, w1e_p, w2e_p, b_1, nullptr, xb_p);
    // layer 2 (spmm gathers bf16 x1; gemm writes fp32 x2)
    k_spmm<<<(NN * 32 + 255) / 256, 256>>>(xb_p, hs_p);
    k_mma<0><<<NTILES, 256, SMEM_MMA>>>(hs_p, ft_p,
                                        w1e_p + DD * DD, w2e_p + DD * DD, b_2, x1_p, nullptr);
    // pooling + decoder
    k_pool<<<NTILES, 128>>>(x1_p, gids);
    k_mlp<<<1, 64>>>(d1w, d1b, d2w, d2b, out);
}

// round 5
// speedup vs baseline: 2.0460x; 1.0186x over previous
#include <cuda_runtime.h>
#include <cuda_bf16.h>
#include <math.h>
#include <stdint.h>

#define NN  100000
#define NE  1600000
#define DD  128
#define NG  64
#define PHH 32
#define NTILES 782   // ceil(NN/128)

// ---------------- device scratch (no allocations allowed) ----------------
__device__ int   g_deg[NN];
__device__ int   g_off[NN + 1];
__device__ int   g_fill[NN];
__device__ int   g_csr[NE];
__device__ int   g_bsum[128];
__device__ int   g_boff[128];
__device__ int   g_gcnt[NG];
__device__ float g_norm[NN];
__device__ float g_pooled[NG * DD];
__device__ float g_hs[NN * DD];             // spmm output (tf32-rounded)
__device__ float g_ft[NN * DD];             // tf32-rounded feature (GEMM f0)
__device__ uint16_t g_fb[NN * DD];          // bf16 feature (L1 gather), then bf16 x2
__device__ uint16_t g_xb[NN * DD];          // bf16 x1 (L2 gather)
__device__ float g_w1e[2][DD * DD];         // effective W1, [n][k], tf32
__device__ float g_w2e[2][DD * DD];         // effective W2 (x0.5), [n][k], tf32

// ---------------- helpers ----------------
__device__ __forceinline__ uint32_t smem_u32(const void* p) {
    uint32_t a;
    asm("{ .reg .u64 t; cvta.to.shared.u64 t, %1; cvt.u32.u64 %0, t; }"
        : "=r"(a) : "l"(p));
    return a;
}

__device__ __forceinline__ float tf32r(float x) {
    uint32_t u;
    asm("cvt.rna.tf32.f32 %0, %1;" : "=r"(u) : "f"(x));
    return __uint_as_float(u);
}

__device__ __forceinline__ uint32_t bf2pack(float lo, float hi) {
    uint32_t p;
    asm("cvt.rn.bf16x2.f32 %0, %1, %2;" : "=r"(p) : "f"(hi), "f"(lo));
    return p;
}

__device__ __forceinline__ void cpa16(uint32_t dst, const float* src) {
    asm volatile("cp.async.cg.shared.global [%0], [%1], 16;"
                 :: "r"(dst), "l"(src) : "memory");
}

__device__ __forceinline__ void ldsm4(uint32_t* r, uint32_t addr) {
    asm volatile("ldmatrix.sync.aligned.m8n8.x4.shared.b16 {%0,%1,%2,%3}, [%4];"
                 : "=r"(r[0]), "=r"(r[1]), "=r"(r[2]), "=r"(r[3]) : "r"(addr));
}

__device__ __forceinline__ void mma8(float* c, const uint32_t* a,
                                     uint32_t b0, uint32_t b1) {
    asm volatile(
        "mma.sync.aligned.m16n8k8.row.col.f32.tf32.tf32.f32 "
        "{%0,%1,%2,%3}, {%4,%5,%6,%7}, {%8,%9}, {%0,%1,%2,%3};"
        : "+f"(c[0]), "+f"(c[1]), "+f"(c[2]), "+f"(c[3])
        : "r"(a[0]), "r"(a[1]), "r"(a[2]), "r"(a[3]), "r"(b0), "r"(b1));
}

__device__ __forceinline__ float bflo(uint32_t u) { return __uint_as_float(u << 16); }
__device__ __forceinline__ float bfhi(uint32_t u) { return __uint_as_float(u & 0xFFFF0000u); }

// ---------------- setup kernels ----------------
__global__ void k_zero() {
    int i = blockIdx.x * blockDim.x + threadIdx.x;
    if (i < NN) { g_deg[i] = 0; g_fill[i] = 0; }
    if (i < NG * DD) g_pooled[i] = 0.f;
    if (i < NG) g_gcnt[i] = 0;
}

__global__ void k_count(const int* __restrict__ dst) {
    int i = blockIdx.x * blockDim.x + threadIdx.x;
    if (i < NE) atomicAdd(&g_deg[dst[i]], 1);
}

__global__ void k_scan1() {
    __shared__ int s[1024];
    int i = blockIdx.x * 1024 + threadIdx.x;
    int v = (i < NN) ? g_deg[i] : 0;
    s[threadIdx.x] = v;
    __syncthreads();
    #pragma unroll
    for (int off = 1; off < 1024; off <<= 1) {
        int t = (threadIdx.x >= off) ? s[threadIdx.x - off] : 0;
        __syncthreads();
        s[threadIdx.x] += t;
        __syncthreads();
    }
    if (i < NN) g_off[i] = s[threadIdx.x] - v;
    if (threadIdx.x == 1023) g_bsum[blockIdx.x] = s[1023];
}

__global__ void k_scan2() {
    __shared__ int s[128];
    int t = threadIdx.x;
    int v = (t < 98) ? g_bsum[t] : 0;
    s[t] = v;
    __syncthreads();
    #pragma unroll
    for (int off = 1; off < 128; off <<= 1) {
        int x = (t >= off) ? s[t - off] : 0;
        __syncthreads();
        s[t] += x;
        __syncthreads();
    }
    g_boff[t] = s[t] - v;
}

__global__ void k_scan3(const int* __restrict__ gids) {
    int i = blockIdx.x * blockDim.x + threadIdx.x;
    if (i < NN) {
        g_off[i] += g_boff[i >> 10];
        g_norm[i] = rsqrtf((float)(g_deg[i] + 1));
        atomicAdd(&g_gcnt[gids[i]], 1);
    }
    if (i == 0) g_off[NN] = NE;
}

__global__ void k_fill(const int* __restrict__ src, const int* __restrict__ dst) {
    int i = blockIdx.x * blockDim.x + threadIdx.x;
    if (i < NE) {
        int d = dst[i];
        int p = g_off[d] + atomicAdd(&g_fill[d], 1);
        g_csr[p] = src[i];
    }
}

// effective weights, transposed to [n][k], tf32-rounded:
//   W1e = (1-b) I + b w1 ;  W2e = 0.5((1-b) I + b w2)
__global__ void k_prep(const float* __restrict__ w11, const float* __restrict__ w21,
                       const float* __restrict__ w12, const float* __restrict__ w22) {
    int n = blockIdx.x, k = threadIdx.x;
    const float B1 = 0.6931471805599453f;  // log 2
    const float B2 = 0.4054651081081644f;  // log 1.5
    float ikn = (k == n) ? 1.f : 0.f;
    g_w1e[0][n * DD + k] = tf32r(B1 * w11[k * DD + n] + (1.f - B1) * ikn);
    g_w2e[0][n * DD + k] = tf32r(0.5f * (B1 * w21[k * DD + n] + (1.f - B1) * ikn));
    g_w1e[1][n * DD + k] = tf32r(B2 * w12[k * DD + n] + (1.f - B2) * ikn);
    g_w2e[1][n * DD + k] = tf32r(0.5f * (B2 * w22[k * DD + n] + (1.f - B2) * ikn));
}

// rounded copies of feature: tf32 (GEMM f0 operand) + bf16 (spmm gather)
__global__ void k_round(const float* __restrict__ fin) {
    int i = blockIdx.x * blockDim.x + threadIdx.x;
    if (i < NN * DD / 4) {
        float4 v = __ldg((const float4*)fin + i);
        ((float4*)g_ft)[i] = make_float4(tf32r(v.x), tf32r(v.y), tf32r(v.z), tf32r(v.w));
        uint2 b;
        b.x = bf2pack(v.x, v.y);
        b.y = bf2pack(v.z, v.w);
        ((uint2*)g_fb)[i] = b;
    }
}

// ---- SpMM (bf16 gather): out = tf32(0.5 * norm ⊙ (A_sl (norm ⊙ in))) ------
// 16-lane node groups (uint4 = 8 bf16/lane), 2 nodes/warp, 4-edge unroll.
__global__ void k_spmm(const uint16_t* __restrict__ fin, float* __restrict__ fout) {
    int gt = blockIdx.x * blockDim.x + threadIdx.x;
    int node = gt >> 4, lane = gt & 15;
    if (node >= NN) return;
    float nrm = g_norm[node];
    const uint4* F = (const uint4*)fin;   // row = 16 x uint4
    uint4 a = __ldg(F + node * 16 + lane);
    float acc[8];
    acc[0] = bflo(a.x) * nrm; acc[1] = bfhi(a.x) * nrm;
    acc[2] = bflo(a.y) * nrm; acc[3] = bfhi(a.y) * nrm;
    acc[4] = bflo(a.z) * nrm; acc[5] = bfhi(a.z) * nrm;
    acc[6] = bflo(a.w) * nrm; acc[7] = bfhi(a.w) * nrm;

    int beg = g_off[node], end = g_off[node + 1];
    int e = beg;
    for (; e + 4 <= end; e += 4) {
        int s0 = __ldg(g_csr + e + 0), s1 = __ldg(g_csr + e + 1);
        int s2 = __ldg(g_csr + e + 2), s3 = __ldg(g_csr + e + 3);
        float n0 = __ldg(g_norm + s0), n1 = __ldg(g_norm + s1);
        float n2 = __ldg(g_norm + s2), n3 = __ldg(g_norm + s3);
        uint4 v0 = __ldg(F + s0 * 16 + lane);
        uint4 v1 = __ldg(F + s1 * 16 + lane);
        uint4 v2 = __ldg(F + s2 * 16 + lane);
        uint4 v3 = __ldg(F + s3 * 16 + lane);
        acc[0] = fmaf(n0, bflo(v0.x), acc[0]); acc[1] = fmaf(n0, bfhi(v0.x), acc[1]);
        acc[2] = fmaf(n0, bflo(v0.y), acc[2]); acc[3] = fmaf(n0, bfhi(v0.y), acc[3]);
        acc[4] = fmaf(n0, bflo(v0.z), acc[4]); acc[5] = fmaf(n0, bfhi(v0.z), acc[5]);
        acc[6] = fmaf(n0, bflo(v0.w), acc[6]); acc[7] = fmaf(n0, bfhi(v0.w), acc[7]);
        acc[0] = fmaf(n1, bflo(v1.x), acc[0]); acc[1] = fmaf(n1, bfhi(v1.x), acc[1]);
        acc[2] = fmaf(n1, bflo(v1.y), acc[2]); acc[3] = fmaf(n1, bfhi(v1.y), acc[3]);
        acc[4] = fmaf(n1, bflo(v1.z), acc[4]); acc[5] = fmaf(n1, bfhi(v1.z), acc[5]);
        acc[6] = fmaf(n1, bflo(v1.w), acc[6]); acc[7] = fmaf(n1, bfhi(v1.w), acc[7]);
        acc[0] = fmaf(n2, bflo(v2.x), acc[0]); acc[1] = fmaf(n2, bfhi(v2.x), acc[1]);
        acc[2] = fmaf(n2, bflo(v2.y), acc[2]); acc[3] = fmaf(n2, bfhi(v2.y), acc[3]);
        acc[4] = fmaf(n2, bflo(v2.z), acc[4]); acc[5] = fmaf(n2, bfhi(v2.z), acc[5]);
        acc[6] = fmaf(n2, bflo(v2.w), acc[6]); acc[7] = fmaf(n2, bfhi(v2.w), acc[7]);
        acc[0] = fmaf(n3, bflo(v3.x), acc[0]); acc[1] = fmaf(n3, bfhi(v3.x), acc[1]);
        acc[2] = fmaf(n3, bflo(v3.y), acc[2]); acc[3] = fmaf(n3, bfhi(v3.y), acc[3]);
        acc[4] = fmaf(n3, bflo(v3.z), acc[4]); acc[5] = fmaf(n3, bfhi(v3.z), acc[5]);
        acc[6] = fmaf(n3, bflo(v3.w), acc[6]); acc[7] = fmaf(n3, bfhi(v3.w), acc[7]);
    }
    for (; e < end; e++) {
        int s0 = __ldg(g_csr + e);
        float n0 = __ldg(g_norm + s0);
        uint4 v0 = __ldg(F + s0 * 16 + lane);
        acc[0] = fmaf(n0, bflo(v0.x), acc[0]); acc[1] = fmaf(n0, bfhi(v0.x), acc[1]);
        acc[2] = fmaf(n0, bflo(v0.y), acc[2]); acc[3] = fmaf(n0, bfhi(v0.y), acc[3]);
        acc[4] = fmaf(n0, bflo(v0.z), acc[4]); acc[5] = fmaf(n0, bfhi(v0.z), acc[5]);
        acc[6] = fmaf(n0, bflo(v0.w), acc[6]); acc[7] = fmaf(n0, bfhi(v0.w), acc[7]);
    }
    float sc = 0.5f * nrm;
    float* O = fout + (size_t)node * DD + lane * 8;
    ((float4*)O)[0] = make_float4(tf32r(acc[0] * sc), tf32r(acc[1] * sc),
                                  tf32r(acc[2] * sc), tf32r(acc[3] * sc));
    ((float4*)O)[1] = make_float4(tf32r(acc[4] * sc), tf32r(acc[5] * sc),
                                  tf32r(acc[6] * sc), tf32r(acc[7] * sc));
}

// ---- tf32 mma.sync GEMM: out_bf16 = relu(hs@W1e + f0@W2e + b) -------------
// BM=128, BN=128, K=256 (hs|f0), BK=32, 8 warps (warp tile 32x64),
// 2-stage cp.async pipeline, SW128 swizzle, ldmatrix fragments, bf16 output.
__global__ void __launch_bounds__(256, 2)
k_mma(const float* __restrict__ Ahs, const float* __restrict__ Af0,
      const float* __restrict__ Bw1, const float* __restrict__ Bw2,
      const float* __restrict__ bias, uint16_t* __restrict__ xbout) {
    extern __shared__ float smem[];   // 2 stages x (A 16KB + B 16KB)
    uint32_t sb = smem_u32(smem);
    int t = threadIdx.x, lane = t & 31, w = t >> 5;
    int wm = (w & 3) * 32, wn = (w >> 2) * 64;
    int R0 = blockIdx.x * 128;

    float acc[2][8][4];
    #pragma unroll
    for (int mt = 0; mt < 2; mt++)
        #pragma unroll
        for (int j = 0; j < 8; j++)
            #pragma unroll
            for (int q = 0; q < 4; q++) acc[mt][j][q] = 0.f;

    auto load_chunk = [&](int c) {
        int s = c & 1;
        uint32_t aB = sb + s * 32768;
        uint32_t bB = aB + 16384;
        const float* A = (c < 4) ? Ahs : Af0;
        const float* B = (c < 4) ? Bw1 : Bw2;
        int ko = (c & 3) * 32;
        #pragma unroll
        for (int i = 0; i < 4; i++) {
            int idx = i * 256 + t;            // 0..1023
            int r = idx >> 3, f4 = idx & 7;
            int row = R0 + r; if (row >= NN) row = 0;
            uint32_t off = r * 128 + ((f4 * 16) ^ ((r & 7) << 4));
            cpa16(aB + off, A + (size_t)row * DD + ko + f4 * 4);
            cpa16(bB + off, B + (size_t)r * DD + ko + f4 * 4);
        }
        asm volatile("cp.async.commit_group;" ::: "memory");
    };

    load_chunk(0);
    load_chunk(1);

    int rA[2], rB[4];
    #pragma unroll
    for (int mt = 0; mt < 2; mt++)
        rA[mt] = wm + mt * 16 + (lane & 7) + ((lane >> 3) & 1) * 8;
    #pragma unroll
    for (int nt = 0; nt < 4; nt++)
        rB[nt] = wn + nt * 16 + (lane & 7) + ((lane >> 4) & 1) * 8;
    uint32_t aH = ((lane >> 4) & 1) * 16;
    uint32_t bH = ((lane >> 3) & 1) * 16;

    for (int c = 0; c < 8; c++) {
        int s = c & 1;
        if (c < 7) asm volatile("cp.async.wait_group 1;" ::: "memory");
        else       asm volatile("cp.async.wait_group 0;" ::: "memory");
        __syncthreads();

        uint32_t aB = sb + s * 32768;
        uint32_t bB = aB + 16384;
        #pragma unroll
        for (int kk = 0; kk < 4; kk++) {
            uint32_t a[2][4], b[4][4];
            #pragma unroll
            for (int mt = 0; mt < 2; mt++)
                ldsm4(a[mt], aB + rA[mt] * 128 +
                              (((uint32_t)(kk * 32) + aH) ^ ((rA[mt] & 7) << 4)));
            #pragma unroll
            for (int nt = 0; nt < 4; nt++)
                ldsm4(b[nt], bB + rB[nt] * 128 +
                              (((uint32_t)(kk * 32) + bH) ^ ((rB[nt] & 7) << 4)));
            #pragma unroll
            for (int mt = 0; mt < 2; mt++)
                #pragma unroll
                for (int nt = 0; nt < 4; nt++) {
                    mma8(acc[mt][2 * nt + 0], a[mt], b[nt][0], b[nt][1]);
                    mma8(acc[mt][2 * nt + 1], a[mt], b[nt][2], b[nt][3]);
                }
        }
        __syncthreads();
        if (c + 2 < 8) load_chunk(c + 2);
    }

    // epilogue: bias + relu + bf16 pack
    #pragma unroll
    for (int mt = 0; mt < 2; mt++) {
        int row0 = R0 + wm + mt * 16 + (lane >> 2);
        #pragma unroll
        for (int j = 0; j < 8; j++) {
            int col = wn + j * 8 + (lane & 3) * 2;
            float2 bb = *(const float2*)(bias + col);
            float v0 = fmaxf(acc[mt][j][0] + bb.x, 0.f);
            float v1 = fmaxf(acc[mt][j][1] + bb.y, 0.f);
            float v2 = fmaxf(acc[mt][j][2] + bb.x, 0.f);
            float v3 = fmaxf(acc[mt][j][3] + bb.y, 0.f);
            if (row0 < NN)
                *(uint32_t*)(xbout + (size_t)row0 * DD + col) = bf2pack(v0, v1);
            if (row0 + 8 < NN)
                *(uint32_t*)(xbout + (size_t)(row0 + 8) * DD + col) = bf2pack(v2, v3);
        }
    }
}

// ---------------- pooling: segmented sum over sorted graph_ids (bf16 in) ---
__global__ void k_pool(const uint16_t* __restrict__ x2, const int* __restrict__ gids) {
    int c  = threadIdx.x;             // 128 cols
    int r0 = blockIdx.x * 128;
    int re = min(r0 + 128, NN);
    int curg = -1;
    float s = 0.f;
    for (int r = r0; r < re; r++) {
        int g = __ldg(gids + r);
        float v = __uint_as_float((uint32_t)__ldg(x2 + (size_t)r * DD + c) << 16);
        if (g != curg) {
            if (curg >= 0) atomicAdd(&g_pooled[curg * DD + c], s);
            curg = g; s = 0.f;
        }
        s += v;
    }
    if (curg >= 0) atomicAdd(&g_pooled[curg * DD + c], s);
}

// ---------------- final MLP ----------------
__global__ void k_mlp(const float* __restrict__ d1w, const float* __restrict__ d1b,
                      const float* __restrict__ d2w, const float* __restrict__ d2b,
                      float* __restrict__ out) {
    int b = threadIdx.x;
    if (b >= NG) return;
    float inv = 1.f / fmaxf((float)g_gcnt[b], 1.f);
    float h[PHH];
    #pragma unroll
    for (int p = 0; p < PHH; p++) h[p] = __ldg(d1b + p);
    for (int c = 0; c < DD; c++) {
        float a = g_pooled[b * DD + c] * inv;
        #pragma unroll
        for (int p = 0; p < PHH; p++)
            h[p] = fmaf(a, __ldg(d1w + c * PHH + p), h[p]);
    }
    float z = __ldg(d2b);
    #pragma unroll
    for (int p = 0; p < PHH; p++)
        z = fmaf(fmaxf(h[p], 0.f), __ldg(d2w + p), z);
    out[b] = 1.f / (1.f + expf(-z));
}

// ---------------- launch ----------------
extern "C" void kernel_launch(void* const* d_in, const int* in_sizes, int n_in,
                              void* d_out, int out_size) {
    const float* feature = (const float*)d_in[0];
    const int*   src     = (const int*)d_in[1];
    const int*   dst     = (const int*)d_in[2];
    const int*   gids    = (const int*)d_in[3];
    const float* w1_1    = (const float*)d_in[4];
    const float* w2_1    = (const float*)d_in[5];
    const float* b_1     = (const float*)d_in[6];
    const float* w1_2    = (const float*)d_in[7];
    const float* w2_2    = (const float*)d_in[8];
    const float* b_2     = (const float*)d_in[9];
    const float* d1w     = (const float*)d_in[10];
    const float* d1b     = (const float*)d_in[11];
    const float* d2w     = (const float*)d_in[12];
    const float* d2b     = (const float*)d_in[13];
    float* out = (float*)d_out;

    float *hs_p = nullptr, *ft_p = nullptr, *w1e_p = nullptr, *w2e_p = nullptr;
    uint16_t *fb_p = nullptr, *xb_p = nullptr;
    cudaGetSymbolAddress((void**)&hs_p,  g_hs);
    cudaGetSymbolAddress((void**)&ft_p,  g_ft);
    cudaGetSymbolAddress((void**)&fb_p,  g_fb);
    cudaGetSymbolAddress((void**)&xb_p,  g_xb);
    cudaGetSymbolAddress((void**)&w1e_p, g_w1e);
    cudaGetSymbolAddress((void**)&w2e_p, g_w2e);

    const int SMEM_MMA = 65536;   // 2 stages x (A 16KB + B 16KB)
    cudaFuncSetAttribute(k_mma, cudaFuncAttributeMaxDynamicSharedMemorySize, SMEM_MMA);

    k_zero<<<(NN + 255) / 256, 256>>>();
    k_count<<<(NE + 255) / 256, 256>>>(dst);
    k_scan1<<<98, 1024>>>();
    k_scan2<<<1, 128>>>();
    k_scan3<<<(NN + 255) / 256, 256>>>(gids);
    k_fill<<<(NE + 255) / 256, 256>>>(src, dst);
    k_prep<<<DD, DD>>>(w1_1, w2_1, w1_2, w2_2);
    k_round<<<(NN * DD / 4 + 255) / 256, 256>>>(feature);

    // layer 1: spmm gathers bf16 feature (g_fb); gemm writes bf16 x1 (g_xb)
    k_spmm<<<(NN * 16 + 255) / 256, 256>>>(fb_p, hs_p);
    k_mma<<<NTILES, 256, SMEM_MMA>>>(hs_p, ft_p, w1e_p, w2e_p, b_1, xb_p);
    // layer 2: spmm gathers bf16 x1 (g_xb); gemm writes bf16 x2 into g_fb (reuse)
    k_spmm<<<(NN * 16 + 255) / 256, 256>>>(xb_p, hs_p);
    k_mma<<<NTILES, 256, SMEM_MMA>>>(hs_p, ft_p,
                                     w1e_p + DD * DD, w2e_p + DD * DD, b_2, fb_p);
    // pooling + decoder
    k_pool<<<NTILES, 128>>>(fb_p, gids);
    k_mlp<<<1, 64>>>(d1w, d1b, d2w, d2b, out);
}

// round 6
// speedup vs baseline: 2.4141x; 1.1799x over previous
#include <cuda_runtime.h>
#include <cuda_bf16.h>
#include <math.h>
#include <stdint.h>

#define NN  100000
#define NE  1600000
#define DD  128
#define NG  64
#define PHH 32
#define NTILES 782   // ceil(NN/128)
#define NSB 98       // scan blocks

// ---------------- device scratch (no allocations allowed) ----------------
__device__ int      g_deg[NN];
__device__ int      g_off[NN + 1];
__device__ int      g_fill[NN];
__device__ int      g_csr[NE];
__device__ unsigned g_agg[128];            // lookback aggregates (bit31 = valid)
__device__ int      g_gcnt[NG];
__device__ float    g_norm[NN];
__device__ float    g_pooled[NG * DD];
__device__ uint16_t g_fb[NN * DD];         // bf16 feature (f0 operand + L1 gather)
__device__ uint16_t g_hb[NN * DD];         // bf16 spmm output (GEMM A operand)
__device__ uint16_t g_xb[NN * DD];         // bf16 x1, then bf16 x2
__device__ uint16_t g_w1b[2][DD * DD];     // effective W1 per layer, [n][k], bf16
__device__ uint16_t g_w2b[2][DD * DD];     // effective W2 (x0.5) per layer, bf16

// ---------------- helpers ----------------
__device__ __forceinline__ uint32_t smem_u32(const void* p) {
    uint32_t a;
    asm("{ .reg .u64 t; cvta.to.shared.u64 t, %1; cvt.u32.u64 %0, t; }"
        : "=r"(a) : "l"(p));
    return a;
}

__device__ __forceinline__ uint32_t bf2pack(float lo, float hi) {
    uint32_t p;
    asm("cvt.rn.bf16x2.f32 %0, %1, %2;" : "=r"(p) : "f"(hi), "f"(lo));
    return p;
}

__device__ __forceinline__ uint16_t bf1(float v) {
    return (uint16_t)(bf2pack(v, 0.f) & 0xFFFFu);
}

__device__ __forceinline__ void cpa16(uint32_t dst, const void* src) {
    asm volatile("cp.async.cg.shared.global [%0], [%1], 16;"
                 :: "r"(dst), "l"(src) : "memory");
}

__device__ __forceinline__ void ldsm4(uint32_t* r, uint32_t addr) {
    asm volatile("ldmatrix.sync.aligned.m8n8.x4.shared.b16 {%0,%1,%2,%3}, [%4];"
                 : "=r"(r[0]), "=r"(r[1]), "=r"(r[2]), "=r"(r[3]) : "r"(addr));
}

__device__ __forceinline__ void mma16(float* c, const uint32_t* a,
                                      uint32_t b0, uint32_t b1) {
    asm volatile(
        "mma.sync.aligned.m16n8k16.row.col.f32.bf16.bf16.f32 "
        "{%0,%1,%2,%3}, {%4,%5,%6,%7}, {%8,%9}, {%0,%1,%2,%3};"
        : "+f"(c[0]), "+f"(c[1]), "+f"(c[2]), "+f"(c[3])
        : "r"(a[0]), "r"(a[1]), "r"(a[2]), "r"(a[3]), "r"(b0), "r"(b1));
}

__device__ __forceinline__ float bflo(uint32_t u) { return __uint_as_float(u << 16); }
__device__ __forceinline__ float bfhi(uint32_t u) { return __uint_as_float(u & 0xFFFF0000u); }

// ---------------- setup ----------------
__global__ void k_zero() {
    int i = blockIdx.x * blockDim.x + threadIdx.x;
    if (i < NN) { g_deg[i] = 0; g_fill[i] = 0; }
    if (i < NG * DD) g_pooled[i] = 0.f;
    if (i < NG) g_gcnt[i] = 0;
    if (i < 128) g_agg[i] = 0u;
}

// fused: degree count + bf16 feature copy + effective-weight prep
__global__ void k_pre(const float* __restrict__ feat, const int* __restrict__ dst,
                      const float* __restrict__ w11, const float* __restrict__ w21,
                      const float* __restrict__ w12, const float* __restrict__ w22) {
    int i = blockIdx.x * blockDim.x + threadIdx.x;
    if (i < NE) atomicAdd(&g_deg[dst[i]], 1);
    if (i < NN * DD / 4) {
        float4 v = __ldg((const float4*)feat + i);
        uint2 b;
        b.x = bf2pack(v.x, v.y);
        b.y = bf2pack(v.z, v.w);
        ((uint2*)g_fb)[i] = b;
    }
    if (i < DD * DD) {
        const float B1 = 0.6931471805599453f;  // log 2
        const float B2 = 0.4054651081081644f;  // log 1.5
        int n = i >> 7, k = i & 127;
        float ikn = (k == n) ? 1.f : 0.f;
        g_w1b[0][n * DD + k] = bf1(B1 * w11[k * DD + n] + (1.f - B1) * ikn);
        g_w2b[0][n * DD + k] = bf1(0.5f * (B1 * w21[k * DD + n] + (1.f - B1) * ikn));
        g_w1b[1][n * DD + k] = bf1(B2 * w12[k * DD + n] + (1.f - B2) * ikn);
        g_w2b[1][n * DD + k] = bf1(0.5f * (B2 * w22[k * DD + n] + (1.f - B2) * ikn));
    }
}

// fused scan: block-local scan + warp-parallel aggregate lookback + norm/gcnt
__global__ void k_scan(const int* __restrict__ gids) {
    __shared__ int s[1024];
    __shared__ int blockoff;
    int b = blockIdx.x, t = threadIdx.x;
    int i = b * 1024 + t;
    int v = (i < NN) ? g_deg[i] : 0;
    s[t] = v;
    __syncthreads();
    #pragma unroll
    for (int off = 1; off < 1024; off <<= 1) {
        int x = (t >= off) ? s[t - off] : 0;
        __syncthreads();
        s[t] += x;
        __syncthreads();
    }
    // publish aggregate, then sum all predecessor aggregates (warp-parallel poll)
    if (t == 1023)
        atomicExch(&g_agg[b], 0x80000000u | (unsigned)s[1023]);
    if (t < 32) {
        int sum = 0;
        for (int base = 0; base < b; base += 32) {
            int idx = base + t;
            unsigned val = 0;
            if (idx < b) {
                do { val = *(volatile unsigned*)&g_agg[idx]; }
                while (!(val & 0x80000000u));
            }
            sum += (int)(val & 0x7FFFFFFFu);
        }
        #pragma unroll
        for (int o = 16; o > 0; o >>= 1)
            sum += __shfl_down_sync(0xFFFFFFFFu, sum, o);
        if (t == 0) blockoff = sum;
    }
    __syncthreads();
    if (i < NN) {
        g_off[i] = blockoff + s[t] - v;
        g_norm[i] = rsqrtf((float)(v + 1));   // +1 self loop
        atomicAdd(&g_gcnt[gids[i]], 1);
    }
    if (i == NN) g_off[NN] = NE;
}

__global__ void k_fill(const int* __restrict__ src, const int* __restrict__ dst) {
    int i = blockIdx.x * blockDim.x + threadIdx.x;
    if (i < NE) {
        int d = dst[i];
        int p = g_off[d] + atomicAdd(&g_fill[d], 1);
        g_csr[p] = src[i];
    }
}

// ---- SpMM (bf16 in/out): out = bf16(0.5 * norm ⊙ (A_sl (norm ⊙ in))) -----
// 16-lane node groups (uint4 = 8 bf16/lane), 2 nodes/warp, 4-edge unroll.
__global__ void k_spmm(const uint16_t* __restrict__ fin, uint16_t* __restrict__ fout) {
    int gt = blockIdx.x * blockDim.x + threadIdx.x;
    int node = gt >> 4, lane = gt & 15;
    if (node >= NN) return;
    float nrm = g_norm[node];
    const uint4* F = (const uint4*)fin;   // row = 16 x uint4
    uint4 a = __ldg(F + node * 16 + lane);
    float acc[8];
    acc[0] = bflo(a.x) * nrm; acc[1] = bfhi(a.x) * nrm;
    acc[2] = bflo(a.y) * nrm; acc[3] = bfhi(a.y) * nrm;
    acc[4] = bflo(a.z) * nrm; acc[5] = bfhi(a.z) * nrm;
    acc[6] = bflo(a.w) * nrm; acc[7] = bfhi(a.w) * nrm;

    int beg = g_off[node], end = g_off[node + 1];
    int e = beg;
    for (; e + 4 <= end; e += 4) {
        int s0 = __ldg(g_csr + e + 0), s1 = __ldg(g_csr + e + 1);
        int s2 = __ldg(g_csr + e + 2), s3 = __ldg(g_csr + e + 3);
        float n0 = __ldg(g_norm + s0), n1 = __ldg(g_norm + s1);
        float n2 = __ldg(g_norm + s2), n3 = __ldg(g_norm + s3);
        uint4 v0 = __ldg(F + s0 * 16 + lane);
        uint4 v1 = __ldg(F + s1 * 16 + lane);
        uint4 v2 = __ldg(F + s2 * 16 + lane);
        uint4 v3 = __ldg(F + s3 * 16 + lane);
        acc[0] = fmaf(n0, bflo(v0.x), acc[0]); acc[1] = fmaf(n0, bfhi(v0.x), acc[1]);
        acc[2] = fmaf(n0, bflo(v0.y), acc[2]); acc[3] = fmaf(n0, bfhi(v0.y), acc[3]);
        acc[4] = fmaf(n0, bflo(v0.z), acc[4]); acc[5] = fmaf(n0, bfhi(v0.z), acc[5]);
        acc[6] = fmaf(n0, bflo(v0.w), acc[6]); acc[7] = fmaf(n0, bfhi(v0.w), acc[7]);
        acc[0] = fmaf(n1, bflo(v1.x), acc[0]); acc[1] = fmaf(n1, bfhi(v1.x), acc[1]);
        acc[2] = fmaf(n1, bflo(v1.y), acc[2]); acc[3] = fmaf(n1, bfhi(v1.y), acc[3]);
        acc[4] = fmaf(n1, bflo(v1.z), acc[4]); acc[5] = fmaf(n1, bfhi(v1.z), acc[5]);
        acc[6] = fmaf(n1, bflo(v1.w), acc[6]); acc[7] = fmaf(n1, bfhi(v1.w), acc[7]);
        acc[0] = fmaf(n2, bflo(v2.x), acc[0]); acc[1] = fmaf(n2, bfhi(v2.x), acc[1]);
        acc[2] = fmaf(n2, bflo(v2.y), acc[2]); acc[3] = fmaf(n2, bfhi(v2.y), acc[3]);
        acc[4] = fmaf(n2, bflo(v2.z), acc[4]); acc[5] = fmaf(n2, bfhi(v2.z), acc[5]);
        acc[6] = fmaf(n2, bflo(v2.w), acc[6]); acc[7] = fmaf(n2, bfhi(v2.w), acc[7]);
        acc[0] = fmaf(n3, bflo(v3.x), acc[0]); acc[1] = fmaf(n3, bfhi(v3.x), acc[1]);
        acc[2] = fmaf(n3, bflo(v3.y), acc[2]); acc[3] = fmaf(n3, bfhi(v3.y), acc[3]);
        acc[4] = fmaf(n3, bflo(v3.z), acc[4]); acc[5] = fmaf(n3, bfhi(v3.z), acc[5]);
        acc[6] = fmaf(n3, bflo(v3.w), acc[6]); acc[7] = fmaf(n3, bfhi(v3.w), acc[7]);
    }
    for (; e < end; e++) {
        int s0 = __ldg(g_csr + e);
        float n0 = __ldg(g_norm + s0);
        uint4 v0 = __ldg(F + s0 * 16 + lane);
        acc[0] = fmaf(n0, bflo(v0.x), acc[0]); acc[1] = fmaf(n0, bfhi(v0.x), acc[1]);
        acc[2] = fmaf(n0, bflo(v0.y), acc[2]); acc[3] = fmaf(n0, bfhi(v0.y), acc[3]);
        acc[4] = fmaf(n0, bflo(v0.z), acc[4]); acc[5] = fmaf(n0, bfhi(v0.z), acc[5]);
        acc[6] = fmaf(n0, bflo(v0.w), acc[6]); acc[7] = fmaf(n0, bfhi(v0.w), acc[7]);
    }
    float sc = 0.5f * nrm;
    uint4 o;
    o.x = bf2pack(acc[0] * sc, acc[1] * sc);
    o.y = bf2pack(acc[2] * sc, acc[3] * sc);
    o.z = bf2pack(acc[4] * sc, acc[5] * sc);
    o.w = bf2pack(acc[6] * sc, acc[7] * sc);
    ((uint4*)fout)[node * 16 + lane] = o;
}

// ---- bf16 mma.sync GEMM: out_bf16 = relu(hs@W1e + f0@W2e + b) -------------
// BM=128, BN=128, K=256 (hs|f0), BK=64 bf16 (128B rows), 4 chunks,
// 8 warps (warp tile 32x64), 2-stage cp.async pipeline, SW128 swizzle.
__global__ void __launch_bounds__(256, 2)
k_mma(const uint16_t* __restrict__ Ahs, const uint16_t* __restrict__ Af0,
      const uint16_t* __restrict__ Bw1, const uint16_t* __restrict__ Bw2,
      const float* __restrict__ bias, uint16_t* __restrict__ xbout) {
    extern __shared__ float smem[];   // 2 stages x (A 16KB + B 16KB)
    uint32_t sb = smem_u32(smem);
    int t = threadIdx.x, lane = t & 31, w = t >> 5;
    int wm = (w & 3) * 32, wn = (w >> 2) * 64;
    int R0 = blockIdx.x * 128;

    float acc[2][8][4];
    #pragma unroll
    for (int mt = 0; mt < 2; mt++)
        #pragma unroll
        for (int j = 0; j < 8; j++)
            #pragma unroll
            for (int q = 0; q < 4; q++) acc[mt][j][q] = 0.f;

    auto load_chunk = [&](int c) {
        int s = c & 1;
        uint32_t aB = sb + s * 32768;
        uint32_t bB = aB + 16384;
        const uint16_t* A = (c < 2) ? Ahs : Af0;
        const uint16_t* B = (c < 2) ? Bw1 : Bw2;
        int ko = (c & 1) * 64;              // bf16 k offset
        #pragma unroll
        for (int i = 0; i < 4; i++) {
            int idx = i * 256 + t;          // 0..1023
            int r = idx >> 3, f4 = idx & 7;
            int row = R0 + r; if (row >= NN) row = 0;
            uint32_t off = r * 128 + ((f4 * 16) ^ ((r & 7) << 4));
            cpa16(aB + off, A + (size_t)row * DD + ko + f4 * 8);
            cpa16(bB + off, B + (size_t)r * DD + ko + f4 * 8);
        }
        asm volatile("cp.async.commit_group;" ::: "memory");
    };

    load_chunk(0);
    load_chunk(1);

    int rA[2], rB[4];
    #pragma unroll
    for (int mt = 0; mt < 2; mt++)
        rA[mt] = wm + mt * 16 + (lane & 7) + ((lane >> 3) & 1) * 8;
    #pragma unroll
    for (int nt = 0; nt < 4; nt++)
        rB[nt] = wn + nt * 16 + (lane & 7) + ((lane >> 4) & 1) * 8;
    uint32_t aH = ((lane >> 4) & 1) * 16;   // A: k-half (k8-15) from bit4
    uint32_t bH = ((lane >> 3) & 1) * 16;   // B: k-half from bit3

    for (int c = 0; c < 4; c++) {
        int s = c & 1;
        if (c < 3) asm volatile("cp.async.wait_group 1;" ::: "memory");
        else       asm volatile("cp.async.wait_group 0;" ::: "memory");
        __syncthreads();

        uint32_t aB = sb + s * 32768;
        uint32_t bB = aB + 16384;
        #pragma unroll
        for (int kk = 0; kk < 4; kk++) {    // 16 k per step
            uint32_t a[2][4], b[4][4];
            #pragma unroll
            for (int mt = 0; mt < 2; mt++)
                ldsm4(a[mt], aB + rA[mt] * 128 +
                              (((uint32_t)(kk * 32) + aH) ^ ((rA[mt] & 7) << 4)));
            #pragma unroll
            for (int nt = 0; nt < 4; nt++)
                ldsm4(b[nt], bB + rB[nt] * 128 +
                              (((uint32_t)(kk * 32) + bH) ^ ((rB[nt] & 7) << 4)));
            #pragma unroll
            for (int mt = 0; mt < 2; mt++)
                #pragma unroll
                for (int nt = 0; nt < 4; nt++) {
                    mma16(acc[mt][2 * nt + 0], a[mt], b[nt][0], b[nt][1]);
                    mma16(acc[mt][2 * nt + 1], a[mt], b[nt][2], b[nt][3]);
                }
        }
        __syncthreads();
        if (c + 2 < 4) load_chunk(c + 2);
    }

    // epilogue: bias + relu + bf16 pack
    #pragma unroll
    for (int mt = 0; mt < 2; mt++) {
        int row0 = R0 + wm + mt * 16 + (lane >> 2);
        #pragma unroll
        for (int j = 0; j < 8; j++) {
            int col = wn + j * 8 + (lane & 3) * 2;
            float2 bb = *(const float2*)(bias + col);
            float v0 = fmaxf(acc[mt][j][0] + bb.x, 0.f);
            float v1 = fmaxf(acc[mt][j][1] + bb.y, 0.f);
            float v2 = fmaxf(acc[mt][j][2] + bb.x, 0.f);
            float v3 = fmaxf(acc[mt][j][3] + bb.y, 0.f);
            if (row0 < NN)
                *(uint32_t*)(xbout + (size_t)row0 * DD + col) = bf2pack(v0, v1);
            if (row0 + 8 < NN)
                *(uint32_t*)(xbout + (size_t)(row0 + 8) * DD + col) = bf2pack(v2, v3);
        }
    }
}

// ---------------- pooling: segmented sum over sorted graph_ids (bf16 in) ---
__global__ void k_pool(const uint16_t* __restrict__ x2, const int* __restrict__ gids) {
    int c  = threadIdx.x;             // 128 cols
    int r0 = blockIdx.x * 128;
    int re = min(r0 + 128, NN);
    int curg = -1;
    float s = 0.f;
    for (int r = r0; r < re; r++) {
        int g = __ldg(gids + r);
        float v = __uint_as_float((uint32_t)__ldg(x2 + (size_t)r * DD + c) << 16);
        if (g != curg) {
            if (curg >= 0) atomicAdd(&g_pooled[curg * DD + c], s);
            curg = g; s = 0.f;
        }
        s += v;
    }
    if (curg >= 0) atomicAdd(&g_pooled[curg * DD + c], s);
}

// ---------------- final MLP ----------------
__global__ void k_mlp(const float* __restrict__ d1w, const float* __restrict__ d1b,
                      const float* __restrict__ d2w, const float* __restrict__ d2b,
                      float* __restrict__ out) {
    int b = threadIdx.x;
    if (b >= NG) return;
    float inv = 1.f / fmaxf((float)g_gcnt[b], 1.f);
    float h[PHH];
    #pragma unroll
    for (int p = 0; p < PHH; p++) h[p] = __ldg(d1b + p);
    for (int c = 0; c < DD; c++) {
        float a = g_pooled[b * DD + c] * inv;
        #pragma unroll
        for (int p = 0; p < PHH; p++)
            h[p] = fmaf(a, __ldg(d1w + c * PHH + p), h[p]);
    }
    float z = __ldg(d2b);
    #pragma unroll
    for (int p = 0; p < PHH; p++)
        z = fmaf(fmaxf(h[p], 0.f), __ldg(d2w + p), z);
    out[b] = 1.f / (1.f + expf(-z));
}

// ---------------- launch ----------------
extern "C" void kernel_launch(void* const* d_in, const int* in_sizes, int n_in,
                              void* d_out, int out_size) {
    const float* feature = (const float*)d_in[0];
    const int*   src     = (const int*)d_in[1];
    const int*   dst     = (const int*)d_in[2];
    const int*   gids    = (const int*)d_in[3];
    const float* w1_1    = (const float*)d_in[4];
    const float* w2_1    = (const float*)d_in[5];
    const float* b_1     = (const float*)d_in[6];
    const float* w1_2    = (const float*)d_in[7];
    const float* w2_2    = (const float*)d_in[8];
    const float* b_2     = (const float*)d_in[9];
    const float* d1w     = (const float*)d_in[10];
    const float* d1b     = (const float*)d_in[11];
    const float* d2w     = (const float*)d_in[12];
    const float* d2b     = (const float*)d_in[13];
    float* out = (float*)d_out;

    uint16_t *fb_p = nullptr, *hb_p = nullptr, *xb_p = nullptr;
    uint16_t *w1b_p = nullptr, *w2b_p = nullptr;
    cudaGetSymbolAddress((void**)&fb_p,  g_fb);
    cudaGetSymbolAddress((void**)&hb_p,  g_hb);
    cudaGetSymbolAddress((void**)&xb_p,  g_xb);
    cudaGetSymbolAddress((void**)&w1b_p, g_w1b);
    cudaGetSymbolAddress((void**)&w2b_p, g_w2b);

    const int SMEM_MMA = 65536;   // 2 stages x (A 16KB + B 16KB)
    cudaFuncSetAttribute(k_mma, cudaFuncAttributeMaxDynamicSharedMemorySize, SMEM_MMA);

    k_zero<<<(NN + 255) / 256, 256>>>();
    k_pre<<<(NN * DD / 4 + 255) / 256, 256>>>(feature, dst, w1_1, w2_1, w1_2, w2_2);
    k_scan<<<NSB, 1024>>>(gids);
    k_fill<<<(NE + 255) / 256, 256>>>(src, dst);

    // layer 1: spmm fb->hb ; gemm (hb, fb) -> xb (bf16 x1)
    k_spmm<<<(NN * 16 + 255) / 256, 256>>>(fb_p, hb_p);
    k_mma<<<NTILES, 256, SMEM_MMA>>>(hb_p, fb_p, w1b_p, w2b_p, b_1, xb_p);
    // layer 2: spmm xb->hb ; gemm (hb, fb) -> xb (bf16 x2, overwrite)
    k_spmm<<<(NN * 16 + 255) / 256, 256>>>(xb_p, hb_p);
    k_mma<<<NTILES, 256, SMEM_MMA>>>(hb_p, fb_p,
                                     w1b_p + DD * DD, w2b_p + DD * DD, b_2, xb_p);
    // pooling + decoder
    k_pool<<<NTILES, 128>>>(xb_p, gids);
    k_mlp<<<1, 64>>>(d1w, d1b, d2w, d2b, out);
}